// round 16
// baseline (speedup 1.0000x reference)
#include <cuda_runtime.h>
#include <cstdint>
#include <math.h>

// Single kernel. Cluster of CS CTAs (256 thr) = one batch b.
// CS=16 (non-portable, 1024 CTAs = 8192 warps = 86% occ) with runtime
// cluster dims; falls back to CS=8 (proven R15) if the launch is rejected.
// Dot inner loop = exact R7 body. Batch-wide max/sum via DSMEM mailboxes +
// barrier.cluster. No gpu-scope atomics.

template <int CS>
__global__ void __launch_bounds__(256)
attn_cluster_kernel(const float* __restrict__ hidden,   // [64, 1024]
                    const float* __restrict__ enc,      // [2048, 64, 1024]
                    float* __restrict__ out)            // [64, 2048]
{
    constexpr int ROWS = 2048 / CS;        // rows per CTA
    constexpr int RPW  = ROWS / 8;         // rows per warp

    __shared__ float4 sh_h[256];           // hidden[b], 4KB
    __shared__ float  sh_e[ROWS];          // this CTA's energies
    __shared__ float  red[8];
    __shared__ float  mailM[16];
    __shared__ float  mailS[16];

    int tid  = threadIdx.x;
    int warp = tid >> 5;
    int lane = tid & 31;

    unsigned int rank;
    asm("mov.u32 %0, %%cluster_ctarank;" : "=r"(rank));
    int b = blockIdx.x / CS;

    sh_h[tid] = reinterpret_cast<const float4*>(hidden + (size_t)b * 1024)[tid];
    __syncthreads();

    // ---- dot (R7 inner body): warp w -> rows rank*ROWS + w*RPW .. +RPW-1 ----
    int s0 = (int)rank * ROWS + warp * RPW;
    for (int r = 0; r < RPW; r++) {
        const float4* row = reinterpret_cast<const float4*>(
            enc + ((size_t)(s0 + r) * 64 + b) * 1024);
        float acc = 0.0f;
#pragma unroll
        for (int i = 0; i < 8; i++) {
            float4 e  = __ldcs(&row[lane + i * 32]);
            float4 hv = sh_h[lane + i * 32];
            acc = fmaf(e.x, hv.x, acc);
            acc = fmaf(e.y, hv.y, acc);
            acc = fmaf(e.z, hv.z, acc);
            acc = fmaf(e.w, hv.w, acc);
        }
#pragma unroll
        for (int o = 16; o; o >>= 1)
            acc += __shfl_xor_sync(0xffffffffu, acc, o);
        if (lane == 0)
            sh_e[warp * RPW + r] = acc;
    }
    __syncthreads();

    // ---- local max over ROWS values ----
    float m = -INFINITY;
    for (int i = tid; i < ROWS; i += 256)
        m = fmaxf(m, sh_e[i]);
#pragma unroll
    for (int o = 16; o; o >>= 1)
        m = fmaxf(m, __shfl_xor_sync(0xffffffffu, m, o));
    if (lane == 0) red[warp] = m;
    __syncthreads();
    if (tid == 0) {
        float x = red[0];
#pragma unroll
        for (int i = 1; i < 8; i++) x = fmaxf(x, red[i]);
        unsigned int la = (unsigned int)__cvta_generic_to_shared(&mailM[rank]);
        for (unsigned int t = 0; t < (unsigned)CS; t++) {
            unsigned int pa;
            asm("mapa.shared::cluster.u32 %0, %1, %2;"
                : "=r"(pa) : "r"(la), "r"(t));
            asm volatile("st.shared::cluster.f32 [%0], %1;"
                         :: "r"(pa), "f"(x) : "memory");
        }
    }
    asm volatile("barrier.cluster.arrive.aligned;" ::: "memory");
    asm volatile("barrier.cluster.wait.aligned;"   ::: "memory");
    float gm = mailM[0];
#pragma unroll
    for (int i = 1; i < CS; i++) gm = fmaxf(gm, mailM[i]);

    // ---- exp + local sum ----
    float s = 0.0f;
    for (int i = tid; i < ROWS; i += 256) {
        float e = __expf(sh_e[i] - gm);
        sh_e[i] = e;
        s += e;
    }
#pragma unroll
    for (int o = 16; o; o >>= 1)
        s += __shfl_xor_sync(0xffffffffu, s, o);
    if (lane == 0) red[warp] = s;
    __syncthreads();
    if (tid == 0) {
        float x = red[0];
#pragma unroll
        for (int i = 1; i < 8; i++) x += red[i];
        unsigned int la = (unsigned int)__cvta_generic_to_shared(&mailS[rank]);
        for (unsigned int t = 0; t < (unsigned)CS; t++) {
            unsigned int pa;
            asm("mapa.shared::cluster.u32 %0, %1, %2;"
                : "=r"(pa) : "r"(la), "r"(t));
            asm volatile("st.shared::cluster.f32 [%0], %1;"
                         :: "r"(pa), "f"(x) : "memory");
        }
    }
    asm volatile("barrier.cluster.arrive.aligned;" ::: "memory");
    asm volatile("barrier.cluster.wait.aligned;"   ::: "memory");
    float gs = mailS[0];
#pragma unroll
    for (int i = 1; i < CS; i++) gs += mailS[i];
    float inv = 1.0f / gs;

    // ---- write this CTA's probabilities (coalesced) ----
    for (int i = tid; i < ROWS; i += 256)
        out[(size_t)b * 2048 + rank * ROWS + i] = sh_e[i] * inv;
}

extern "C" void kernel_launch(void* const* d_in, const int* in_sizes, int n_in,
                              void* d_out, int out_size)
{
    const float* hidden = (const float*)d_in[0];   // [1, 64, 1024]
    const float* enc    = (const float*)d_in[1];   // [2048, 64, 1024]
    float* out          = (float*)d_out;           // [64, 1, 2048]

    // Try 16-CTA clusters (1024 CTAs, 8192 warps).
    cudaFuncSetAttribute(attn_cluster_kernel<16>,
                         cudaFuncAttributeNonPortableClusterSizeAllowed, 1);

    cudaLaunchConfig_t cfg = {};
    cfg.gridDim  = dim3(64 * 16, 1, 1);
    cfg.blockDim = dim3(256, 1, 1);
    cfg.dynamicSmemBytes = 0;
    cfg.stream = 0;
    cudaLaunchAttribute attrs[1];
    attrs[0].id = cudaLaunchAttributeClusterDimension;
    attrs[0].val.clusterDim = {16, 1, 1};
    cfg.attrs = attrs;
    cfg.numAttrs = 1;

    cudaError_t err = cudaLaunchKernelEx(&cfg, attn_cluster_kernel<16>,
                                         hidden, enc, out);
    if (err != cudaSuccess) {
        (void)cudaGetLastError();   // clear
        // Fallback: proven cluster-8 shape (R15).
        cudaLaunchConfig_t cfg8 = {};
        cfg8.gridDim  = dim3(64 * 8, 1, 1);
        cfg8.blockDim = dim3(256, 1, 1);
        cfg8.dynamicSmemBytes = 0;
        cfg8.stream = 0;
        cudaLaunchAttribute a8[1];
        a8[0].id = cudaLaunchAttributeClusterDimension;
        a8[0].val.clusterDim = {8, 1, 1};
        cfg8.attrs = a8;
        cfg8.numAttrs = 1;
        cudaLaunchKernelEx(&cfg8, attn_cluster_kernel<8>, hidden, enc, out);
    }
}

// round 17
// speedup vs baseline: 1.0380x; 1.0380x over previous
#include <cuda_runtime.h>
#include <cstdint>
#include <math.h>

// Two kernels, fine-grained per-batch handoff with PER-CTA arrivals.
// R8's 2x regression came from 131072 per-warp RMWs on 2 cache lines; here:
// 16384 arrivals total (1 per dot CTA), counters padded 128B apart, spread
// across the kernel's 75us. Dot body = exact R7 (best measured streamer).

struct Pad { unsigned int v; unsigned int pad[31]; };   // 128B per counter
__device__ Pad g_cnt[64];                               // zero-init

__global__ void __launch_bounds__(256) dot_kernel(
    const float* __restrict__ hidden,   // [64, 1024]
    const float* __restrict__ enc,      // [2048, 64, 1024]
    float* __restrict__ energies)       // [64, 2048]
{
    cudaTriggerProgrammaticLaunchCompletion();

    __shared__ float4 sh_h[256];        // hidden[b] : 4KB

    int b      = blockIdx.x >> 8;       // b-major: batch b done ~(b+1)/64 in
    int schunk = blockIdx.x & 255;

    sh_h[threadIdx.x] =
        reinterpret_cast<const float4*>(hidden + (size_t)b * 1024)[threadIdx.x];
    __syncthreads();

    int warp = threadIdx.x >> 5;
    int lane = threadIdx.x & 31;
    int s    = schunk * 8 + warp;

    const float4* row = reinterpret_cast<const float4*>(
        enc + ((size_t)s * 64 + b) * 1024);

    float acc = 0.0f;
#pragma unroll
    for (int i = 0; i < 8; i++) {
        float4 e  = __ldcs(&row[lane + i * 32]);
        float4 hv = sh_h[lane + i * 32];
        acc = fmaf(e.x, hv.x, acc);
        acc = fmaf(e.y, hv.y, acc);
        acc = fmaf(e.z, hv.z, acc);
        acc = fmaf(e.w, hv.w, acc);
    }
#pragma unroll
    for (int o = 16; o; o >>= 1)
        acc += __shfl_xor_sync(0xffffffffu, acc, o);

    if (lane == 0)
        asm volatile("st.global.cg.f32 [%0], %1;"
                     :: "l"(energies + b * 2048 + s), "f"(acc) : "memory");

    // ONE arrival per CTA: all 8 warps' stores must be issued first.
    __syncthreads();
    if (threadIdx.x == 0)
        asm volatile("red.release.gpu.global.add.u32 [%0], %1;"
                     :: "l"(&g_cnt[b].v), "r"(1u) : "memory");
}

// Warp-per-batch softmax; spins (acquire) until its 256 dot CTAs arrived.
__global__ void __launch_bounds__(32) softmax_kernel(float* __restrict__ out)
{
    int b    = blockIdx.x;
    int lane = threadIdx.x;
    float* p = out + (size_t)b * 2048;

    if (lane == 0) {
        unsigned int v;
        do {
            __nanosleep(128);
            asm volatile("ld.acquire.gpu.global.u32 %0, [%1];"
                         : "=r"(v) : "l"(&g_cnt[b].v) : "memory");
        } while (v < 256u);
    }
    __syncwarp();

    const float4* pv = reinterpret_cast<const float4*>(p);
    float4 v[16];
#pragma unroll
    for (int i = 0; i < 16; i++)
        v[i] = __ldcg(&pv[lane + i * 32]);

    float m = -INFINITY;
#pragma unroll
    for (int i = 0; i < 16; i++)
        m = fmaxf(m, fmaxf(fmaxf(v[i].x, v[i].y), fmaxf(v[i].z, v[i].w)));
#pragma unroll
    for (int o = 16; o; o >>= 1)
        m = fmaxf(m, __shfl_xor_sync(0xffffffffu, m, o));

    float s = 0.0f;
#pragma unroll
    for (int i = 0; i < 16; i++) {
        v[i].x = __expf(v[i].x - m);
        v[i].y = __expf(v[i].y - m);
        v[i].z = __expf(v[i].z - m);
        v[i].w = __expf(v[i].w - m);
        s += (v[i].x + v[i].y) + (v[i].z + v[i].w);
    }
#pragma unroll
    for (int o = 16; o; o >>= 1)
        s += __shfl_xor_sync(0xffffffffu, s, o);
    float inv = 1.0f / s;

    float4* pw = reinterpret_cast<float4*>(p);
#pragma unroll
    for (int i = 0; i < 16; i++) {
        float4 w = v[i];
        w.x *= inv; w.y *= inv; w.z *= inv; w.w *= inv;
        pw[lane + i * 32] = w;
    }

    // reset for next graph replay (next dot launch is stream-ordered after us)
    if (lane == 0) g_cnt[b].v = 0u;
}

extern "C" void kernel_launch(void* const* d_in, const int* in_sizes, int n_in,
                              void* d_out, int out_size)
{
    const float* hidden = (const float*)d_in[0];   // [1, 64, 1024]
    const float* enc    = (const float*)d_in[1];   // [2048, 64, 1024]
    float* out          = (float*)d_out;           // [64, 1, 2048]

    dot_kernel<<<16384, 256>>>(hidden, enc, out);

    // PDL: softmax CTAs resident early; per-batch spin does fine ordering.
    cudaLaunchConfig_t cfg = {};
    cfg.gridDim  = dim3(64, 1, 1);
    cfg.blockDim = dim3(32, 1, 1);
    cfg.dynamicSmemBytes = 0;
    cfg.stream = 0;
    cudaLaunchAttribute attrs[1];
    attrs[0].id = cudaLaunchAttributeProgrammaticStreamSerialization;
    attrs[0].val.programmaticStreamSerializationAllowed = 1;
    cfg.attrs = attrs;
    cfg.numAttrs = 1;
    cudaLaunchKernelEx(&cfg, softmax_kernel, out);
}